// round 2
// baseline (speedup 1.0000x reference)
#include <cuda_runtime.h>

// Scratch: lgn transposed to channel-last [b][y][x][c] (4*64*64*64 f32 = 4MB)
__device__ float g_lgn_cl[4 * 64 * 64 * 64];

// ---------------------------------------------------------------------------
// Kernel 1: transpose lgn (B,C,H,W) -> (B,H,W,C), tiled via shared memory.
// grid (xTiles=2, y=64, b=4), block 256.
// ---------------------------------------------------------------------------
__global__ void transpose_lgn_kernel(const float* __restrict__ lgn) {
    __shared__ float sh[64][33];
    const int x0  = blockIdx.x * 32;
    const int y   = blockIdx.y;
    const int b   = blockIdx.z;
    const int tid = threadIdx.x;

    // coalesced load: warp reads 32 consecutive x for one channel
    const int cL = tid >> 5, xL = tid & 31;
#pragma unroll
    for (int r = 0; r < 8; r++) {
        const int c = cL + r * 8;
        sh[c][xL] = lgn[(((b * 64 + c) * 64 + y) * 64) + x0 + xL];
    }
    __syncthreads();

    // coalesced store: consecutive threads write consecutive channels
    const int cS = tid & 63, xb = tid >> 6;
#pragma unroll
    for (int r = 0; r < 8; r++) {
        const int x = xb + r * 4;
        g_lgn_cl[(((b * 64 + y) * 64 + (x0 + x)) * 64) + cS] = sh[cS][x];
    }
}

// ---------------------------------------------------------------------------
// Kernel 2: main fused compute.
// Block = 512 threads = 32 pixels (lane) x 16 nv (warp). Grid = 512 blocks.
// Shared coef layouts (transposed so the NS axis is the slow one and the
// trailing 4-vector is contiguous -> one LDS.128 per interp corner row):
//   sx[nv][n][j][kp]  = coefx[nv][j][kp][n]   (y-axis interp, rows j, comps kp)
//   sy[nv][m][kp][k]  = coefy[nv][kp][k][m]   (z-axis interp, rows kp, comps k)
//   sr[nv][o][k][l]   = coefr[nv][k][l][o]    (x-axis interp, rows k,  comps l)
// ---------------------------------------------------------------------------
__global__ __launch_bounds__(512) void seprot_main_kernel(
    const float* __restrict__ grid1, const float* __restrict__ grid2,
    const float* __restrict__ theta,
    const float* __restrict__ coefx, const float* __restrict__ coefy,
    const float* __restrict__ coefr, float* __restrict__ out)
{
    __shared__ float4 sx[16 * 16 * 4];
    __shared__ float4 sy[16 * 16 * 4];
    __shared__ float4 sr[16 * 16 * 4];

    const int tid = threadIdx.x;

    // cooperative transposed load of all three coefficient tensors
#pragma unroll
    for (int it = 0; it < 8; it++) {
        const int g  = tid + it * 512;
        const int nv = g >> 8;
        const int a  = (g >> 6) & 3;   // j / kp / k   (2nd index of coef*)
        const int c2 = (g >> 4) & 3;   // kp / k / l   (3rd index)
        const int n  = g & 15;         // NS index (last)
        const int dst = (((nv * 16 + n) * 4 + a) * 4) + c2;
        ((float*)sx)[dst] = coefx[g];
        ((float*)sy)[dst] = coefy[g];
        ((float*)sr)[dst] = coefr[g];
    }
    __syncthreads();

    const int nv   = tid >> 5;
    const int lane = tid & 31;
    const int P    = blockIdx.x * 32 + lane;   // global pixel id
    const int b    = P >> 12;                  // 4096 pixels per batch
    const int rem  = P & 4095;                 // h*64 + w

    const float2 g2 = *((const float2*)grid2 + P);
    const float fx = rintf((g2.x + 1.0f) * 32.0f - 0.5f);
    const float fy = rintf((g2.y + 1.0f) * 32.0f - 0.5f);
    const bool qv = (fx >= 0.0f) && (fx <= 63.0f) && (fy >= 0.0f) && (fy <= 63.0f);

    // ---- Cy: z interp (depends only on b) ----
    const float zc  = theta[b] / 3.14159265358979323846f;
    const float gz  = (zc + 1.0f) * 8.0f - 0.5f;
    const float z0f = floorf(gz);
    const int   z0  = (int)z0f;
    const float wz1 = gz - z0f;
    const float wz0e = (z0 >= 0 && z0 <= 15) ? (1.0f - wz1) : 0.0f;
    const float wz1e = (z0 + 1 >= 0 && z0 + 1 <= 15) ? wz1 : 0.0f;
    const int iz0 = min(max(z0, 0), 15);
    const int iz1 = min(max(z0 + 1, 0), 15);

    float4 Cy[4];
#pragma unroll
    for (int kp = 0; kp < 4; kp++) {
        const float4 a0 = sy[(nv * 16 + iz0) * 4 + kp];
        const float4 a1 = sy[(nv * 16 + iz1) * 4 + kp];
        Cy[kp].x = wz0e * a0.x + wz1e * a1.x;
        Cy[kp].y = wz0e * a0.y + wz1e * a1.y;
        Cy[kp].z = wz0e * a0.z + wz1e * a1.z;
        Cy[kp].w = wz0e * a0.w + wz1e * a1.w;
    }

    float acc0 = 0.0f, acc1 = 0.0f, acc2 = 0.0f, acc3 = 0.0f;

    if (qv) {
        const int qx = (int)fx, qy = (int)fy;
        const float4* lbase = (const float4*)g_lgn_cl + (size_t)b * (4096 * 16);

#pragma unroll
        for (int di = -1; di <= 1; di++) {
#pragma unroll
            for (int dj = -1; dj <= 1; dj++) {
                const int ty = qy + di, tx = qx + dj;
                if ((unsigned)ty < 64u && (unsigned)tx < 64u) {
                    const float2 g1 = *((const float2*)grid1 + ((b * 64 + ty) * 64 + tx));
                    const float dx = g2.x - g1.x;
                    const float dy = g2.y - g1.y;

                    // ---- x-axis interp -> Cr (coefr) ----
                    const float gx  = (dx + 1.0f) * 8.0f - 0.5f;
                    const float x0f = floorf(gx);
                    const int   x0  = (int)x0f;
                    const float wx1 = gx - x0f;
                    const float wx0e = (x0 >= 0 && x0 <= 15) ? (1.0f - wx1) : 0.0f;
                    const float wx1e = (x0 + 1 >= 0 && x0 + 1 <= 15) ? wx1 : 0.0f;
                    const int ix0 = min(max(x0, 0), 15);
                    const int ix1 = min(max(x0 + 1, 0), 15);

                    // lgn taps for this nv (4 contiguous channels)
                    const float4 L = lbase[(ty * 64 + tx) * 16 + nv];

                    // v[k] = (Cr @ L)[k]
                    float v0, v1, v2, v3;
                    {
                        const int base0 = (nv * 16 + ix0) * 4;
                        const int base1 = (nv * 16 + ix1) * 4;
                        float4 r0, r1;
                        r0 = sr[base0 + 0]; r1 = sr[base1 + 0];
                        v0 = wx0e * (r0.x*L.x + r0.y*L.y + r0.z*L.z + r0.w*L.w)
                           + wx1e * (r1.x*L.x + r1.y*L.y + r1.z*L.z + r1.w*L.w);
                        r0 = sr[base0 + 1]; r1 = sr[base1 + 1];
                        v1 = wx0e * (r0.x*L.x + r0.y*L.y + r0.z*L.z + r0.w*L.w)
                           + wx1e * (r1.x*L.x + r1.y*L.y + r1.z*L.z + r1.w*L.w);
                        r0 = sr[base0 + 2]; r1 = sr[base1 + 2];
                        v2 = wx0e * (r0.x*L.x + r0.y*L.y + r0.z*L.z + r0.w*L.w)
                           + wx1e * (r1.x*L.x + r1.y*L.y + r1.z*L.z + r1.w*L.w);
                        r0 = sr[base0 + 3]; r1 = sr[base1 + 3];
                        v3 = wx0e * (r0.x*L.x + r0.y*L.y + r0.z*L.z + r0.w*L.w)
                           + wx1e * (r1.x*L.x + r1.y*L.y + r1.z*L.z + r1.w*L.w);
                    }

                    // u[kp] = (Cy @ v)[kp]
                    const float u0 = Cy[0].x*v0 + Cy[0].y*v1 + Cy[0].z*v2 + Cy[0].w*v3;
                    const float u1 = Cy[1].x*v0 + Cy[1].y*v1 + Cy[1].z*v2 + Cy[1].w*v3;
                    const float u2 = Cy[2].x*v0 + Cy[2].y*v1 + Cy[2].z*v2 + Cy[2].w*v3;
                    const float u3 = Cy[3].x*v0 + Cy[3].y*v1 + Cy[3].z*v2 + Cy[3].w*v3;

                    // ---- y-axis interp -> Cx (coefx), fused with accumulation ----
                    const float gy  = (dy + 1.0f) * 8.0f - 0.5f;
                    const float y0f = floorf(gy);
                    const int   y0  = (int)y0f;
                    const float wy1 = gy - y0f;
                    const float wy0e = (y0 >= 0 && y0 <= 15) ? (1.0f - wy1) : 0.0f;
                    const float wy1e = (y0 + 1 >= 0 && y0 + 1 <= 15) ? wy1 : 0.0f;
                    const int iy0 = min(max(y0, 0), 15);
                    const int iy1 = min(max(y0 + 1, 0), 15);

                    const int bx0 = (nv * 16 + iy0) * 4;
                    const int bx1 = (nv * 16 + iy1) * 4;
                    {
                        float4 c0, c1;
                        c0 = sx[bx0 + 0]; c1 = sx[bx1 + 0];
                        acc0 += (wy0e*c0.x + wy1e*c1.x) * u0 + (wy0e*c0.y + wy1e*c1.y) * u1
                              + (wy0e*c0.z + wy1e*c1.z) * u2 + (wy0e*c0.w + wy1e*c1.w) * u3;
                        c0 = sx[bx0 + 1]; c1 = sx[bx1 + 1];
                        acc1 += (wy0e*c0.x + wy1e*c1.x) * u0 + (wy0e*c0.y + wy1e*c1.y) * u1
                              + (wy0e*c0.z + wy1e*c1.z) * u2 + (wy0e*c0.w + wy1e*c1.w) * u3;
                        c0 = sx[bx0 + 2]; c1 = sx[bx1 + 2];
                        acc2 += (wy0e*c0.x + wy1e*c1.x) * u0 + (wy0e*c0.y + wy1e*c1.y) * u1
                              + (wy0e*c0.z + wy1e*c1.z) * u2 + (wy0e*c0.w + wy1e*c1.w) * u3;
                        c0 = sx[bx0 + 3]; c1 = sx[bx1 + 3];
                        acc3 += (wy0e*c0.x + wy1e*c1.x) * u0 + (wy0e*c0.y + wy1e*c1.y) * u1
                              + (wy0e*c0.z + wy1e*c1.z) * u2 + (wy0e*c0.w + wy1e*c1.w) * u3;
                    }
                }
            }
        }
    }

    // out layout (B, NV*VL, H, W): channel = nv*4 + i, pixel = rem
    float* o = out + ((size_t)(b * 64 + nv * 4)) * 4096 + rem;
    o[0]        = acc0;
    o[4096]     = acc1;
    o[2 * 4096] = acc2;
    o[3 * 4096] = acc3;
}

extern "C" void kernel_launch(void* const* d_in, const int* in_sizes, int n_in,
                              void* d_out, int out_size) {
    const float* grid1 = (const float*)d_in[0];
    const float* grid2 = (const float*)d_in[1];
    const float* theta = (const float*)d_in[2];
    const float* lgn   = (const float*)d_in[3];
    const float* coefx = (const float*)d_in[4];
    const float* coefy = (const float*)d_in[5];
    const float* coefr = (const float*)d_in[6];
    float* out = (float*)d_out;

    transpose_lgn_kernel<<<dim3(2, 64, 4), 256>>>(lgn);
    seprot_main_kernel<<<512, 512>>>(grid1, grid2, theta, coefx, coefy, coefr, out);
}

// round 3
// speedup vs baseline: 1.6889x; 1.6889x over previous
#include <cuda_runtime.h>

// Scratch: lgn transposed to channel-last [b][y][x][c] (4*64*64*64 f32 = 4MB)
__device__ float g_lgn_cl[4 * 64 * 64 * 64];

// ---------------------------------------------------------------------------
// Kernel 1: transpose lgn (B,C,H,W) -> (B,H,W,C), tiled via shared memory.
// ---------------------------------------------------------------------------
__global__ void transpose_lgn_kernel(const float* __restrict__ lgn) {
    __shared__ float sh[64][33];
    const int x0  = blockIdx.x * 32;
    const int y   = blockIdx.y;
    const int b   = blockIdx.z;
    const int tid = threadIdx.x;

    const int cL = tid >> 5, xL = tid & 31;
#pragma unroll
    for (int r = 0; r < 8; r++) {
        const int c = cL + r * 8;
        sh[c][xL] = lgn[(((b * 64 + c) * 64 + y) * 64) + x0 + xL];
    }
    __syncthreads();

    const int cS = tid & 63, xb = tid >> 6;
#pragma unroll
    for (int r = 0; r < 8; r++) {
        const int x = xb + r * 4;
        g_lgn_cl[(((b * 64 + y) * 64 + (x0 + x)) * 64) + cS] = sh[cS][x];
    }
}

// ---------------------------------------------------------------------------
// Kernel 2: main fused compute.
// Block = 512 threads = 32 pixels (lane) x 16 nv (warp). Grid = 512 blocks.
// Shared coef tables, float4 entries, XOR bank swizzle:
//   logical entry (nv, row, slot) with 4 components
//   physical float4 index = (nv*16 + row)*4 + (slot ^ ((row>>1)&3))
// This spreads the data-dependent 'row' gather across all 8 bank groups
// (conflict degree <= 2 instead of up to 16).
// ---------------------------------------------------------------------------
__global__ __launch_bounds__(512) void seprot_main_kernel(
    const float* __restrict__ grid1, const float* __restrict__ grid2,
    const float* __restrict__ theta,
    const float* __restrict__ coefx, const float* __restrict__ coefy,
    const float* __restrict__ coefr, float* __restrict__ out)
{
    __shared__ float4 sx[16 * 16 * 4];
    __shared__ float4 sy[16 * 16 * 4];
    __shared__ float4 sr[16 * 16 * 4];

    const int tid = threadIdx.x;

    // cooperative transposed + swizzled load of all three coefficient tensors
#pragma unroll
    for (int it = 0; it < 8; it++) {
        const int g  = tid + it * 512;
        const int nv = g >> 8;
        const int a  = (g >> 6) & 3;   // slot  (2nd index of coef*)
        const int c2 = (g >> 4) & 3;   // component (3rd index)
        const int n  = g & 15;         // row = NS index (last)
        const int entry = (nv * 16 + n) * 4 + (a ^ ((n >> 1) & 3));
        const int dst = entry * 4 + c2;
        ((float*)sx)[dst] = coefx[g];
        ((float*)sy)[dst] = coefy[g];
        ((float*)sr)[dst] = coefr[g];
    }
    __syncthreads();

    const int nv   = tid >> 5;
    const int lane = tid & 31;
    const int P    = blockIdx.x * 32 + lane;   // global pixel id
    const int b    = P >> 12;                  // 4096 pixels per batch
    const int rem  = P & 4095;                 // h*64 + w

    const float2 g2 = *((const float2*)grid2 + P);
    const float fx = rintf((g2.x + 1.0f) * 32.0f - 0.5f);
    const float fy = rintf((g2.y + 1.0f) * 32.0f - 0.5f);
    const bool qv = (fx >= 0.0f) && (fx <= 63.0f) && (fy >= 0.0f) && (fy <= 63.0f);

    // ---- Cy: z interp (depends only on b) ----
    const float zc  = theta[b] / 3.14159265358979323846f;
    const float gz  = (zc + 1.0f) * 8.0f - 0.5f;
    const float z0f = floorf(gz);
    const int   z0  = (int)z0f;
    const float wz1 = gz - z0f;
    const float wz0e = (z0 >= 0 && z0 <= 15) ? (1.0f - wz1) : 0.0f;
    const float wz1e = (z0 + 1 >= 0 && z0 + 1 <= 15) ? wz1 : 0.0f;
    const int iz0 = min(max(z0, 0), 15);
    const int iz1 = min(max(z0 + 1, 0), 15);
    const int zs0 = (iz0 >> 1) & 3, zs1 = (iz1 >> 1) & 3;
    const int zb0 = (nv * 16 + iz0) * 4, zb1 = (nv * 16 + iz1) * 4;

    float4 Cy[4];
#pragma unroll
    for (int kp = 0; kp < 4; kp++) {
        const float4 a0 = sy[zb0 + (kp ^ zs0)];
        const float4 a1 = sy[zb1 + (kp ^ zs1)];
        Cy[kp].x = wz0e * a0.x + wz1e * a1.x;
        Cy[kp].y = wz0e * a0.y + wz1e * a1.y;
        Cy[kp].z = wz0e * a0.z + wz1e * a1.z;
        Cy[kp].w = wz0e * a0.w + wz1e * a1.w;
    }

    float acc0 = 0.0f, acc1 = 0.0f, acc2 = 0.0f, acc3 = 0.0f;

    if (qv) {
        const int qx = (int)fx, qy = (int)fy;
        const float4* lbase = (const float4*)g_lgn_cl + (size_t)b * (4096 * 16);

#pragma unroll
        for (int di = -1; di <= 1; di++) {
#pragma unroll
            for (int dj = -1; dj <= 1; dj++) {
                const int ty = qy + di, tx = qx + dj;
                if ((unsigned)ty < 64u && (unsigned)tx < 64u) {
                    const float2 g1 = *((const float2*)grid1 + ((b * 64 + ty) * 64 + tx));
                    const float dx = g2.x - g1.x;
                    const float dy = g2.y - g1.y;

                    // ---- x-axis interp -> Cr (coefr) ----
                    const float gx  = (dx + 1.0f) * 8.0f - 0.5f;
                    const float x0f = floorf(gx);
                    const int   x0  = (int)x0f;
                    const float wx1 = gx - x0f;
                    const float wx0e = (x0 >= 0 && x0 <= 15) ? (1.0f - wx1) : 0.0f;
                    const float wx1e = (x0 + 1 >= 0 && x0 + 1 <= 15) ? wx1 : 0.0f;
                    const int ix0 = min(max(x0, 0), 15);
                    const int ix1 = min(max(x0 + 1, 0), 15);
                    const int rs0 = (ix0 >> 1) & 3, rs1 = (ix1 >> 1) & 3;
                    const int rb0 = (nv * 16 + ix0) * 4, rb1 = (nv * 16 + ix1) * 4;

                    // lgn taps for this nv (4 contiguous channels)
                    const float4 L = lbase[(ty * 64 + tx) * 16 + nv];

                    // v[k] = (Cr @ L)[k]
                    float v0, v1, v2, v3;
                    {
                        float4 r0, r1;
                        r0 = sr[rb0 + (0 ^ rs0)]; r1 = sr[rb1 + (0 ^ rs1)];
                        v0 = wx0e * (r0.x*L.x + r0.y*L.y + r0.z*L.z + r0.w*L.w)
                           + wx1e * (r1.x*L.x + r1.y*L.y + r1.z*L.z + r1.w*L.w);
                        r0 = sr[rb0 + (1 ^ rs0)]; r1 = sr[rb1 + (1 ^ rs1)];
                        v1 = wx0e * (r0.x*L.x + r0.y*L.y + r0.z*L.z + r0.w*L.w)
                           + wx1e * (r1.x*L.x + r1.y*L.y + r1.z*L.z + r1.w*L.w);
                        r0 = sr[rb0 + (2 ^ rs0)]; r1 = sr[rb1 + (2 ^ rs1)];
                        v2 = wx0e * (r0.x*L.x + r0.y*L.y + r0.z*L.z + r0.w*L.w)
                           + wx1e * (r1.x*L.x + r1.y*L.y + r1.z*L.z + r1.w*L.w);
                        r0 = sr[rb0 + (3 ^ rs0)]; r1 = sr[rb1 + (3 ^ rs1)];
                        v3 = wx0e * (r0.x*L.x + r0.y*L.y + r0.z*L.z + r0.w*L.w)
                           + wx1e * (r1.x*L.x + r1.y*L.y + r1.z*L.z + r1.w*L.w);
                    }

                    // u[kp] = (Cy @ v)[kp]
                    const float u0 = Cy[0].x*v0 + Cy[0].y*v1 + Cy[0].z*v2 + Cy[0].w*v3;
                    const float u1 = Cy[1].x*v0 + Cy[1].y*v1 + Cy[1].z*v2 + Cy[1].w*v3;
                    const float u2 = Cy[2].x*v0 + Cy[2].y*v1 + Cy[2].z*v2 + Cy[2].w*v3;
                    const float u3 = Cy[3].x*v0 + Cy[3].y*v1 + Cy[3].z*v2 + Cy[3].w*v3;

                    // ---- y-axis interp -> Cx (coefx), fused with accumulation ----
                    const float gy  = (dy + 1.0f) * 8.0f - 0.5f;
                    const float y0f = floorf(gy);
                    const int   y0  = (int)y0f;
                    const float wy1 = gy - y0f;
                    const float wy0e = (y0 >= 0 && y0 <= 15) ? (1.0f - wy1) : 0.0f;
                    const float wy1e = (y0 + 1 >= 0 && y0 + 1 <= 15) ? wy1 : 0.0f;
                    const int iy0 = min(max(y0, 0), 15);
                    const int iy1 = min(max(y0 + 1, 0), 15);
                    const int ts0 = (iy0 >> 1) & 3, ts1 = (iy1 >> 1) & 3;
                    const int bx0 = (nv * 16 + iy0) * 4, bx1 = (nv * 16 + iy1) * 4;
                    {
                        float4 c0, c1;
                        c0 = sx[bx0 + (0 ^ ts0)]; c1 = sx[bx1 + (0 ^ ts1)];
                        acc0 += (wy0e*c0.x + wy1e*c1.x) * u0 + (wy0e*c0.y + wy1e*c1.y) * u1
                              + (wy0e*c0.z + wy1e*c1.z) * u2 + (wy0e*c0.w + wy1e*c1.w) * u3;
                        c0 = sx[bx0 + (1 ^ ts0)]; c1 = sx[bx1 + (1 ^ ts1)];
                        acc1 += (wy0e*c0.x + wy1e*c1.x) * u0 + (wy0e*c0.y + wy1e*c1.y) * u1
                              + (wy0e*c0.z + wy1e*c1.z) * u2 + (wy0e*c0.w + wy1e*c1.w) * u3;
                        c0 = sx[bx0 + (2 ^ ts0)]; c1 = sx[bx1 + (2 ^ ts1)];
                        acc2 += (wy0e*c0.x + wy1e*c1.x) * u0 + (wy0e*c0.y + wy1e*c1.y) * u1
                              + (wy0e*c0.z + wy1e*c1.z) * u2 + (wy0e*c0.w + wy1e*c1.w) * u3;
                        c0 = sx[bx0 + (3 ^ ts0)]; c1 = sx[bx1 + (3 ^ ts1)];
                        acc3 += (wy0e*c0.x + wy1e*c1.x) * u0 + (wy0e*c0.y + wy1e*c1.y) * u1
                              + (wy0e*c0.z + wy1e*c1.z) * u2 + (wy0e*c0.w + wy1e*c1.w) * u3;
                    }
                }
            }
        }
    }

    // out layout (B, NV*VL, H, W): channel = nv*4 + i, pixel = rem
    float* o = out + ((size_t)(b * 64 + nv * 4)) * 4096 + rem;
    o[0]        = acc0;
    o[4096]     = acc1;
    o[2 * 4096] = acc2;
    o[3 * 4096] = acc3;
}

extern "C" void kernel_launch(void* const* d_in, const int* in_sizes, int n_in,
                              void* d_out, int out_size) {
    const float* grid1 = (const float*)d_in[0];
    const float* grid2 = (const float*)d_in[1];
    const float* theta = (const float*)d_in[2];
    const float* lgn   = (const float*)d_in[3];
    const float* coefx = (const float*)d_in[4];
    const float* coefy = (const float*)d_in[5];
    const float* coefr = (const float*)d_in[6];
    float* out = (float*)d_out;

    transpose_lgn_kernel<<<dim3(2, 64, 4), 256>>>(lgn);
    seprot_main_kernel<<<512, 512>>>(grid1, grid2, theta, coefx, coefy, coefr, out);
}

// round 6
// speedup vs baseline: 2.1646x; 1.2816x over previous
#include <cuda_runtime.h>

// Scratch: lgn transposed to channel-last [b][y][x][c] (4*64*64*64 f32 = 4MB)
__device__ float g_lgn_cl[4 * 64 * 64 * 64];

// ---------------------------------------------------------------------------
// Kernel 1: transpose lgn (B,C,H,W) -> (B,H,W,C), tiled via shared memory.
// ---------------------------------------------------------------------------
__global__ void transpose_lgn_kernel(const float* __restrict__ lgn) {
    __shared__ float sh[64][33];
    const int x0  = blockIdx.x * 32;
    const int y   = blockIdx.y;
    const int b   = blockIdx.z;
    const int tid = threadIdx.x;

    const int cL = tid >> 5, xL = tid & 31;
#pragma unroll
    for (int r = 0; r < 8; r++) {
        const int c = cL + r * 8;
        sh[c][xL] = lgn[(((b * 64 + c) * 64 + y) * 64) + x0 + xL];
    }
    __syncthreads();

    const int cS = tid & 63, xb = tid >> 6;
#pragma unroll
    for (int r = 0; r < 8; r++) {
        const int x = xb + r * 4;
        g_lgn_cl[(((b * 64 + y) * 64 + (x0 + x)) * 64) + cS] = sh[cS][x];
    }
}

// ---------------------------------------------------------------------------
// Kernel 2: main fused compute.
// Block = 512 threads = 32 pixels x 16 nv.  Thread: pl = tid>>4, nv = tid&15.
// Warp = 2 pixels x 16 nv  ->  lgn gather is 2x256B contiguous per tap,
// grid1/grid2 are warp-broadcast.
// Shared coef tables, float4 entries, layout [row][nv][slot] with swizzle
//   physical float4 index = row*64 + nv*4 + (slot ^ ((nv>>1)&3))
// -> bank group = (nv&1)*4 + (slot^((nv>>1)&3)) covers all 8 groups as nv
// varies across lanes: conflict degree <= 2.
// Output staged through smem (aliases sy after prologue) for coalesced STG.
// ---------------------------------------------------------------------------
__global__ __launch_bounds__(512, 2) void seprot_main_kernel(
    const float* __restrict__ grid1, const float* __restrict__ grid2,
    const float* __restrict__ theta,
    const float* __restrict__ coefx, const float* __restrict__ coefy,
    const float* __restrict__ coefr, float* __restrict__ out)
{
    __shared__ float4 sx[1024];
    __shared__ float4 sy[1024];
    __shared__ float4 sr[1024];

    const int tid = threadIdx.x;

    // cooperative transposed + swizzled load of all three coefficient tensors
#pragma unroll
    for (int it = 0; it < 8; it++) {
        const int g   = tid + it * 512;
        const int nvq = g >> 8;
        const int a   = (g >> 6) & 3;   // slot  (2nd index of coef*)
        const int c2  = (g >> 4) & 3;   // component (3rd index)
        const int n   = g & 15;         // row = NS index (last)
        const int entry = n * 64 + nvq * 4 + (a ^ ((nvq >> 1) & 3));
        const int dst = entry * 4 + c2;
        ((float*)sx)[dst] = coefx[g];
        ((float*)sy)[dst] = coefy[g];
        ((float*)sr)[dst] = coefr[g];
    }
    __syncthreads();

    const int nv  = tid & 15;
    const int swz = (nv >> 1) & 3;
    const int nv4 = nv * 4;
    const int pl  = tid >> 4;                  // pixel within block, 0..31
    const int P   = blockIdx.x * 32 + pl;      // global pixel id
    const int b   = blockIdx.x >> 7;           // 128 blocks per batch

    const float2 g2 = ((const float2*)grid2)[P];   // warp-broadcast
    const float fx = rintf((g2.x + 1.0f) * 32.0f - 0.5f);
    const float fy = rintf((g2.y + 1.0f) * 32.0f - 0.5f);
    const bool qv = (fx >= 0.0f) && (fx <= 63.0f) && (fy >= 0.0f) && (fy <= 63.0f);

    // ---- Cy: z interp (depends only on b) ----
    const float zc  = theta[b] / 3.14159265358979323846f;
    const float gz  = (zc + 1.0f) * 8.0f - 0.5f;
    const float z0f = floorf(gz);
    const int   z0  = (int)z0f;
    const float wz1 = gz - z0f;
    const float wz0e = (z0 >= 0 && z0 <= 15) ? (1.0f - wz1) : 0.0f;
    const float wz1e = (z0 + 1 >= 0 && z0 + 1 <= 15) ? wz1 : 0.0f;
    const int iz0 = min(max(z0, 0), 15);
    const int iz1 = min(max(z0 + 1, 0), 15);
    const int zb0 = iz0 * 64 + nv4, zb1 = iz1 * 64 + nv4;

    float4 Cy[4];
#pragma unroll
    for (int kp = 0; kp < 4; kp++) {
        const float4 a0 = sy[zb0 + (kp ^ swz)];
        const float4 a1 = sy[zb1 + (kp ^ swz)];
        Cy[kp].x = wz0e * a0.x + wz1e * a1.x;
        Cy[kp].y = wz0e * a0.y + wz1e * a1.y;
        Cy[kp].z = wz0e * a0.z + wz1e * a1.z;
        Cy[kp].w = wz0e * a0.w + wz1e * a1.w;
    }
    __syncthreads();   // sy is dead from here; its memory is reused as out-stage

    float acc0 = 0.0f, acc1 = 0.0f, acc2 = 0.0f, acc3 = 0.0f;

    if (qv) {
        const int qx = (int)fx, qy = (int)fy;
        const float4* lbase = (const float4*)g_lgn_cl + (size_t)b * (4096 * 16);
        const float2* g1base = (const float2*)grid1 + b * 4096;

#pragma unroll
        for (int di = -1; di <= 1; di++) {
#pragma unroll
            for (int dj = -1; dj <= 1; dj++) {
                const int ty = qy + di, tx = qx + dj;
                if ((unsigned)ty < 64u && (unsigned)tx < 64u) {
                    const float2 g1 = g1base[ty * 64 + tx];   // warp-broadcast
                    const float dx = g2.x - g1.x;
                    const float dy = g2.y - g1.y;

                    // ---- x-axis interp -> Cr (coefr) ----
                    const float gx  = (dx + 1.0f) * 8.0f - 0.5f;
                    const float x0f = floorf(gx);
                    const int   x0  = (int)x0f;
                    const float wx1 = gx - x0f;
                    const float wx0e = (x0 >= 0 && x0 <= 15) ? (1.0f - wx1) : 0.0f;
                    const float wx1e = (x0 + 1 >= 0 && x0 + 1 <= 15) ? wx1 : 0.0f;
                    const int ix0 = min(max(x0, 0), 15);
                    const int ix1 = min(max(x0 + 1, 0), 15);
                    const int rb0 = ix0 * 64 + nv4, rb1 = ix1 * 64 + nv4;

                    // lgn taps for this nv: 16 lanes -> 256B contiguous
                    const float4 L = lbase[(ty * 64 + tx) * 16 + nv];

                    // v[k] = (Cr @ L)[k]
                    float v0, v1, v2, v3;
                    {
                        float4 r0, r1;
                        r0 = sr[rb0 + (0 ^ swz)]; r1 = sr[rb1 + (0 ^ swz)];
                        v0 = wx0e * (r0.x*L.x + r0.y*L.y + r0.z*L.z + r0.w*L.w)
                           + wx1e * (r1.x*L.x + r1.y*L.y + r1.z*L.z + r1.w*L.w);
                        r0 = sr[rb0 + (1 ^ swz)]; r1 = sr[rb1 + (1 ^ swz)];
                        v1 = wx0e * (r0.x*L.x + r0.y*L.y + r0.z*L.z + r0.w*L.w)
                           + wx1e * (r1.x*L.x + r1.y*L.y + r1.z*L.z + r1.w*L.w);
                        r0 = sr[rb0 + (2 ^ swz)]; r1 = sr[rb1 + (2 ^ swz)];
                        v2 = wx0e * (r0.x*L.x + r0.y*L.y + r0.z*L.z + r0.w*L.w)
                           + wx1e * (r1.x*L.x + r1.y*L.y + r1.z*L.z + r1.w*L.w);
                        r0 = sr[rb0 + (3 ^ swz)]; r1 = sr[rb1 + (3 ^ swz)];
                        v3 = wx0e * (r0.x*L.x + r0.y*L.y + r0.z*L.z + r0.w*L.w)
                           + wx1e * (r1.x*L.x + r1.y*L.y + r1.z*L.z + r1.w*L.w);
                    }

                    // u[kp] = (Cy @ v)[kp]
                    const float u0 = Cy[0].x*v0 + Cy[0].y*v1 + Cy[0].z*v2 + Cy[0].w*v3;
                    const float u1 = Cy[1].x*v0 + Cy[1].y*v1 + Cy[1].z*v2 + Cy[1].w*v3;
                    const float u2 = Cy[2].x*v0 + Cy[2].y*v1 + Cy[2].z*v2 + Cy[2].w*v3;
                    const float u3 = Cy[3].x*v0 + Cy[3].y*v1 + Cy[3].z*v2 + Cy[3].w*v3;

                    // ---- y-axis interp -> Cx (coefx), fused with accumulation ----
                    const float gy  = (dy + 1.0f) * 8.0f - 0.5f;
                    const float y0f = floorf(gy);
                    const int   y0  = (int)y0f;
                    const float wy1 = gy - y0f;
                    const float wy0e = (y0 >= 0 && y0 <= 15) ? (1.0f - wy1) : 0.0f;
                    const float wy1e = (y0 + 1 >= 0 && y0 + 1 <= 15) ? wy1 : 0.0f;
                    const int iy0 = min(max(y0, 0), 15);
                    const int iy1 = min(max(y0 + 1, 0), 15);
                    const int bx0 = iy0 * 64 + nv4, bx1 = iy1 * 64 + nv4;
                    {
                        float4 c0, c1;
                        c0 = sx[bx0 + (0 ^ swz)]; c1 = sx[bx1 + (0 ^ swz)];
                        acc0 += (wy0e*c0.x + wy1e*c1.x) * u0 + (wy0e*c0.y + wy1e*c1.y) * u1
                              + (wy0e*c0.z + wy1e*c1.z) * u2 + (wy0e*c0.w + wy1e*c1.w) * u3;
                        c0 = sx[bx0 + (1 ^ swz)]; c1 = sx[bx1 + (1 ^ swz)];
                        acc1 += (wy0e*c0.x + wy1e*c1.x) * u0 + (wy0e*c0.y + wy1e*c1.y) * u1
                              + (wy0e*c0.z + wy1e*c1.z) * u2 + (wy0e*c0.w + wy1e*c1.w) * u3;
                        c0 = sx[bx0 + (2 ^ swz)]; c1 = sx[bx1 + (2 ^ swz)];
                        acc2 += (wy0e*c0.x + wy1e*c1.x) * u0 + (wy0e*c0.y + wy1e*c1.y) * u1
                              + (wy0e*c0.z + wy1e*c1.z) * u2 + (wy0e*c0.w + wy1e*c1.w) * u3;
                        c0 = sx[bx0 + (3 ^ swz)]; c1 = sx[bx1 + (3 ^ swz)];
                        acc3 += (wy0e*c0.x + wy1e*c1.x) * u0 + (wy0e*c0.y + wy1e*c1.y) * u1
                              + (wy0e*c0.z + wy1e*c1.z) * u2 + (wy0e*c0.w + wy1e*c1.w) * u3;
                    }
                }
            }
        }
    }

    // ---- stage outputs in smem (aliasing sy), then coalesced global stores ----
    float* so = (float*)sy;            // needs 64*33 = 2112 floats < 4096 avail
    so[(nv4 + 0) * 33 + pl] = acc0;
    so[(nv4 + 1) * 33 + pl] = acc1;
    so[(nv4 + 2) * 33 + pl] = acc2;
    so[(nv4 + 3) * 33 + pl] = acc3;
    __syncthreads();

    // out layout (B, 64, 64, 64): 32 consecutive pixels per block, same batch
    const int rem0 = (blockIdx.x & 127) * 32;
    float* obase = out + (size_t)b * 64 * 4096 + rem0;
#pragma unroll
    for (int i2 = 0; i2 < 4; i2++) {
        const int idx = tid + i2 * 512;
        const int c = idx >> 5, px = idx & 31;
        obase[(size_t)c * 4096 + px] = so[c * 33 + px];
    }
}

extern "C" void kernel_launch(void* const* d_in, const int* in_sizes, int n_in,
                              void* d_out, int out_size) {
    const float* grid1 = (const float*)d_in[0];
    const float* grid2 = (const float*)d_in[1];
    const float* theta = (const float*)d_in[2];
    const float* lgn   = (const float*)d_in[3];
    const float* coefx = (const float*)d_in[4];
    const float* coefy = (const float*)d_in[5];
    const float* coefr = (const float*)d_in[6];
    float* out = (float*)d_out;

    transpose_lgn_kernel<<<dim3(2, 64, 4), 256>>>(lgn);
    seprot_main_kernel<<<512, 512>>>(grid1, grid2, theta, coefx, coefy, coefr, out);
}

// round 7
// speedup vs baseline: 2.2832x; 1.0548x over previous
#include <cuda_runtime.h>
#include <cuda_fp16.h>

// Scratch: lgn transposed to channel-last [b][y][x][c] (4*64*64*64 f32 = 4MB)
__device__ float g_lgn_cl[4 * 64 * 64 * 64];

// ---------------------------------------------------------------------------
// Kernel 1: transpose lgn (B,C,H,W) -> (B,H,W,C), tiled via shared memory.
// ---------------------------------------------------------------------------
__global__ void transpose_lgn_kernel(const float* __restrict__ lgn) {
    __shared__ float sh[64][33];
    const int x0  = blockIdx.x * 32;
    const int y   = blockIdx.y;
    const int b   = blockIdx.z;
    const int tid = threadIdx.x;

    const int cL = tid >> 5, xL = tid & 31;
#pragma unroll
    for (int r = 0; r < 8; r++) {
        const int c = cL + r * 8;
        sh[c][xL] = lgn[(((b * 64 + c) * 64 + y) * 64) + x0 + xL];
    }
    __syncthreads();

    const int cS = tid & 63, xb = tid >> 6;
#pragma unroll
    for (int r = 0; r < 8; r++) {
        const int x = xb + r * 4;
        g_lgn_cl[(((b * 64 + y) * 64 + (x0 + x)) * 64) + cS] = sh[cS][x];
    }
}

__device__ __forceinline__ float dot4(float4 a, float4 b) {
    return a.x * b.x + a.y * b.y + a.z * b.z + a.w * b.w;
}
// two packed half2 words -> float4
__device__ __forceinline__ float4 rv(unsigned int a, unsigned int b) {
    const float2 lo = __half22float2(*(const __half2*)&a);
    const float2 hi = __half22float2(*(const __half2*)&b);
    return make_float4(lo.x, lo.y, hi.x, hi.y);
}
__device__ __forceinline__ unsigned int pk(float a, float b) {
    __half2 h = __floats2half2_rn(a, b);
    return *(unsigned int*)&h;
}

// ---------------------------------------------------------------------------
// Kernel 2: main fused compute.
// Block = 512 threads = 32 pixels x 16 nv.  Thread: pl = tid>>4, nv = tid&15.
// Prologue: load fp32 tables; compute Cy(z) per nv; fold sr2 = Cy @ Cr[row]
// in fp32; round sr2 and Cx to fp16 tables stored in sy's memory.
// fp16 unit layout: uint4 unit (row, nv, h) holds rows {2h,2h+1} x 4 comps;
// physical index = row*32 + nv*2 + (h ^ ((nv>>2)&1))  -> conflict-free.
// Mainloop per tap: 4+4 LDS.128, convert to fp32, interp + dots in fp32.
// Output staged via smem (aliases sr) for coalesced stores.
// ---------------------------------------------------------------------------
__global__ __launch_bounds__(512, 2) void seprot_main_kernel(
    const float* __restrict__ grid1, const float* __restrict__ grid2,
    const float* __restrict__ theta,
    const float* __restrict__ coefx, const float* __restrict__ coefy,
    const float* __restrict__ coefr, float* __restrict__ out)
{
    __shared__ float4 sx[1024];   // fp32 coefx table (prologue only)
    __shared__ float4 sy[1024];   // fp32 coefy table; later: srh/sxh fp16 tables
    __shared__ float4 sr[1024];   // fp32 coefr table; later: output staging

    const int tid = threadIdx.x;

    // ---- stage 1: cooperative transposed + swizzled fp32 load ----
#pragma unroll
    for (int it = 0; it < 8; it++) {
        const int g   = tid + it * 512;
        const int nvq = g >> 8;
        const int a   = (g >> 6) & 3;   // slot  (2nd index of coef*)
        const int c2  = (g >> 4) & 3;   // component (3rd index)
        const int n   = g & 15;         // row = NS index (last)
        const int entry = n * 64 + nvq * 4 + (a ^ ((nvq >> 1) & 3));
        const int dst = entry * 4 + c2;
        ((float*)sx)[dst] = coefx[g];
        ((float*)sy)[dst] = coefy[g];
        ((float*)sr)[dst] = coefr[g];
    }
    __syncthreads();

    const int nv   = tid & 15;
    const int swz  = (nv >> 1) & 3;
    const int hswz = (nv >> 2) & 1;
    const int nv4  = nv * 4;
    const int nv2  = nv * 2;
    const int pl   = tid >> 4;                 // pixel within block, 0..31
    const int P    = blockIdx.x * 32 + pl;     // global pixel id
    const int b    = blockIdx.x >> 7;          // 128 blocks per batch

    const float2 g2 = ((const float2*)grid2)[P];   // warp-broadcast
    const float fx = rintf((g2.x + 1.0f) * 32.0f - 0.5f);
    const float fy = rintf((g2.y + 1.0f) * 32.0f - 0.5f);
    const bool qv = (fx >= 0.0f) && (fx <= 63.0f) && (fy >= 0.0f) && (fy <= 63.0f);

    // ---- stage 2: Cy (z interp, depends only on b,nv) ----
    const float zc  = theta[b] / 3.14159265358979323846f;
    const float gz  = (zc + 1.0f) * 8.0f - 0.5f;
    const float z0f = floorf(gz);
    const int   z0  = (int)z0f;
    const float wz1 = gz - z0f;
    const float wz0e = (z0 >= 0 && z0 <= 15) ? (1.0f - wz1) : 0.0f;
    const float wz1e = (z0 + 1 >= 0 && z0 + 1 <= 15) ? wz1 : 0.0f;
    const int iz0 = min(max(z0, 0), 15);
    const int iz1 = min(max(z0 + 1, 0), 15);
    const int zb0 = iz0 * 64 + nv4, zb1 = iz1 * 64 + nv4;

    float4 Cy[4];
#pragma unroll
    for (int kp = 0; kp < 4; kp++) {
        const float4 a0 = sy[zb0 + (kp ^ swz)];
        const float4 a1 = sy[zb1 + (kp ^ swz)];
        Cy[kp].x = wz0e * a0.x + wz1e * a1.x;
        Cy[kp].y = wz0e * a0.y + wz1e * a1.y;
        Cy[kp].z = wz0e * a0.z + wz1e * a1.z;
        Cy[kp].w = wz0e * a0.w + wz1e * a1.w;
    }
    __syncthreads();   // all reads of fp32 sy done; its memory is repurposed

    // ---- stage 3: build fp16 tables (into sy's memory) ----
    uint4* srh = (uint4*)sy;           // 512 uint4 = 8KB : folded Cy@Cr
    uint4* sxh = ((uint4*)sy) + 512;   // 512 uint4 = 8KB : Cx
    {
        const int row  = pl >> 1;
        const int h    = pl & 1;
        const int base = row * 64 + nv4;
        const int unit = row * 32 + nv2 + (h ^ hswz);

        // fold: sr2[k][l] = sum_k' Cy[k].(k') * Cr[row][k'][l]
        const float4 S0 = sr[base + (0 ^ swz)];
        const float4 S1 = sr[base + (1 ^ swz)];
        const float4 S2 = sr[base + (2 ^ swz)];
        const float4 S3 = sr[base + (3 ^ swz)];
        float4 R[4];
#pragma unroll
        for (int k = 0; k < 4; k++) {
            R[k].x = Cy[k].x*S0.x + Cy[k].y*S1.x + Cy[k].z*S2.x + Cy[k].w*S3.x;
            R[k].y = Cy[k].x*S0.y + Cy[k].y*S1.y + Cy[k].z*S2.y + Cy[k].w*S3.y;
            R[k].z = Cy[k].x*S0.z + Cy[k].y*S1.z + Cy[k].z*S2.z + Cy[k].w*S3.z;
            R[k].w = Cy[k].x*S0.w + Cy[k].y*S1.w + Cy[k].z*S2.w + Cy[k].w*S3.w;
        }
        const float4 RA = h ? R[2] : R[0];
        const float4 RB = h ? R[3] : R[1];
        uint4 u;
        u.x = pk(RA.x, RA.y); u.y = pk(RA.z, RA.w);
        u.z = pk(RB.x, RB.y); u.w = pk(RB.z, RB.w);
        srh[unit] = u;

        const float4 CA = sx[base + ((2 * h)     ^ swz)];
        const float4 CB = sx[base + ((2 * h + 1) ^ swz)];
        uint4 v;
        v.x = pk(CA.x, CA.y); v.y = pk(CA.z, CA.w);
        v.z = pk(CB.x, CB.y); v.w = pk(CB.z, CB.w);
        sxh[unit] = v;
    }
    __syncthreads();

    float acc0 = 0.0f, acc1 = 0.0f, acc2 = 0.0f, acc3 = 0.0f;

    if (qv) {
        const int qx = (int)fx, qy = (int)fy;
        const float4* lbase = (const float4*)g_lgn_cl + (size_t)b * (4096 * 16);
        const float2* g1base = (const float2*)grid1 + b * 4096;

#pragma unroll
        for (int di = -1; di <= 1; di++) {
#pragma unroll
            for (int dj = -1; dj <= 1; dj++) {
                const int ty = qy + di, tx = qx + dj;
                if ((unsigned)ty < 64u && (unsigned)tx < 64u) {
                    const float2 g1 = g1base[ty * 64 + tx];   // warp-broadcast
                    const float dx = g2.x - g1.x;
                    const float dy = g2.y - g1.y;

                    // ---- x-axis interp over folded table ----
                    const float gx  = (dx + 1.0f) * 8.0f - 0.5f;
                    const float x0f = floorf(gx);
                    const int   x0  = (int)x0f;
                    const float wx1 = gx - x0f;
                    const float wx0e = (x0 >= 0 && x0 <= 15) ? (1.0f - wx1) : 0.0f;
                    const float wx1e = (x0 + 1 >= 0 && x0 + 1 <= 15) ? wx1 : 0.0f;
                    const int ix0 = min(max(x0, 0), 15);
                    const int ix1 = min(max(x0 + 1, 0), 15);

                    // lgn taps for this nv: 16 lanes -> 256B contiguous
                    const float4 L = lbase[(ty * 64 + tx) * 16 + nv];

                    const uint4 U0a = srh[ix0 * 32 + nv2 + (0 ^ hswz)];
                    const uint4 U0b = srh[ix0 * 32 + nv2 + (1 ^ hswz)];
                    const uint4 U1a = srh[ix1 * 32 + nv2 + (0 ^ hswz)];
                    const uint4 U1b = srh[ix1 * 32 + nv2 + (1 ^ hswz)];

                    const float u0 = wx0e * dot4(rv(U0a.x, U0a.y), L)
                                   + wx1e * dot4(rv(U1a.x, U1a.y), L);
                    const float u1 = wx0e * dot4(rv(U0a.z, U0a.w), L)
                                   + wx1e * dot4(rv(U1a.z, U1a.w), L);
                    const float u2 = wx0e * dot4(rv(U0b.x, U0b.y), L)
                                   + wx1e * dot4(rv(U1b.x, U1b.y), L);
                    const float u3 = wx0e * dot4(rv(U0b.z, U0b.w), L)
                                   + wx1e * dot4(rv(U1b.z, U1b.w), L);
                    const float4 u4 = make_float4(u0, u1, u2, u3);

                    // ---- y-axis interp over Cx, fused with accumulation ----
                    const float gy  = (dy + 1.0f) * 8.0f - 0.5f;
                    const float y0f = floorf(gy);
                    const int   y0  = (int)y0f;
                    const float wy1 = gy - y0f;
                    const float wy0e = (y0 >= 0 && y0 <= 15) ? (1.0f - wy1) : 0.0f;
                    const float wy1e = (y0 + 1 >= 0 && y0 + 1 <= 15) ? wy1 : 0.0f;
                    const int iy0 = min(max(y0, 0), 15);
                    const int iy1 = min(max(y0 + 1, 0), 15);

                    const uint4 V0a = sxh[iy0 * 32 + nv2 + (0 ^ hswz)];
                    const uint4 V0b = sxh[iy0 * 32 + nv2 + (1 ^ hswz)];
                    const uint4 V1a = sxh[iy1 * 32 + nv2 + (0 ^ hswz)];
                    const uint4 V1b = sxh[iy1 * 32 + nv2 + (1 ^ hswz)];

                    acc0 += wy0e * dot4(rv(V0a.x, V0a.y), u4)
                          + wy1e * dot4(rv(V1a.x, V1a.y), u4);
                    acc1 += wy0e * dot4(rv(V0a.z, V0a.w), u4)
                          + wy1e * dot4(rv(V1a.z, V1a.w), u4);
                    acc2 += wy0e * dot4(rv(V0b.x, V0b.y), u4)
                          + wy1e * dot4(rv(V1b.x, V1b.y), u4);
                    acc3 += wy0e * dot4(rv(V0b.z, V0b.w), u4)
                          + wy1e * dot4(rv(V1b.z, V1b.w), u4);
                }
            }
        }
    }

    // ---- stage outputs in smem (aliasing sr), then coalesced global stores ----
    float* so = (float*)sr;            // needs 64*33 = 2112 floats < 4096 avail
    __syncthreads();                   // ensure prologue reads of sr are done
    so[(nv4 + 0) * 33 + pl] = acc0;
    so[(nv4 + 1) * 33 + pl] = acc1;
    so[(nv4 + 2) * 33 + pl] = acc2;
    so[(nv4 + 3) * 33 + pl] = acc3;
    __syncthreads();

    // out layout (B, 64, 64, 64): 32 consecutive pixels per block, same batch
    const int rem0 = (blockIdx.x & 127) * 32;
    float* obase = out + (size_t)b * 64 * 4096 + rem0;
#pragma unroll
    for (int i2 = 0; i2 < 4; i2++) {
        const int idx = tid + i2 * 512;
        const int c = idx >> 5, px = idx & 31;
        obase[(size_t)c * 4096 + px] = so[c * 33 + px];
    }
}

extern "C" void kernel_launch(void* const* d_in, const int* in_sizes, int n_in,
                              void* d_out, int out_size) {
    const float* grid1 = (const float*)d_in[0];
    const float* grid2 = (const float*)d_in[1];
    const float* theta = (const float*)d_in[2];
    const float* lgn   = (const float*)d_in[3];
    const float* coefx = (const float*)d_in[4];
    const float* coefy = (const float*)d_in[5];
    const float* coefr = (const float*)d_in[6];
    float* out = (float*)d_out;

    transpose_lgn_kernel<<<dim3(2, 64, 4), 256>>>(lgn);
    seprot_main_kernel<<<512, 512>>>(grid1, grid2, theta, coefx, coefy, coefr, out);
}

// round 8
// speedup vs baseline: 2.3901x; 1.0468x over previous
#include <cuda_runtime.h>
#include <cuda_fp16.h>

// Scratch: lgn transposed to channel-last [b][y][x][c] (4*64*64*64 f32 = 4MB)
__device__ float g_lgn_cl[4 * 64 * 64 * 64];

// ---------------------------------------------------------------------------
// Kernel 1: transpose lgn (B,C,H,W) -> (B,H,W,C), tiled via shared memory.
// ---------------------------------------------------------------------------
__global__ void transpose_lgn_kernel(const float* __restrict__ lgn) {
    __shared__ float sh[64][33];
    const int x0  = blockIdx.x * 32;
    const int y   = blockIdx.y;
    const int b   = blockIdx.z;
    const int tid = threadIdx.x;

    const int cL = tid >> 5, xL = tid & 31;
#pragma unroll
    for (int r = 0; r < 8; r++) {
        const int c = cL + r * 8;
        sh[c][xL] = lgn[(((b * 64 + c) * 64 + y) * 64) + x0 + xL];
    }
    __syncthreads();

    const int cS = tid & 63, xb = tid >> 6;
#pragma unroll
    for (int r = 0; r < 8; r++) {
        const int x = xb + r * 4;
        g_lgn_cl[(((b * 64 + y) * 64 + (x0 + x)) * 64) + cS] = sh[cS][x];
    }
}

__device__ __forceinline__ float dot4(float4 a, float4 b) {
    return a.x * b.x + a.y * b.y + a.z * b.z + a.w * b.w;
}
// two packed half2 words -> float4
__device__ __forceinline__ float4 rv(unsigned int a, unsigned int b) {
    const float2 lo = __half22float2(*(const __half2*)&a);
    const float2 hi = __half22float2(*(const __half2*)&b);
    return make_float4(lo.x, lo.y, hi.x, hi.y);
}
__device__ __forceinline__ unsigned int pk(float a, float b) {
    __half2 h = __floats2half2_rn(a, b);
    return *(unsigned int*)&h;
}

// ---------------------------------------------------------------------------
// Kernel 2: main fused compute.
// Block = 512 threads = 32 pixels x 16 nv.  Thread: pl = tid>>4, nv = tid&15.
// Prologue: load fp32 tables; Cy(z) per nv; fold srh = fp16(Cy @ Cr[row]);
// sxh = fp16(Cx). fp16 unit layout conflict-free across nv lanes.
// Mainloop: BRANCHLESS taps — clamped addresses, validity folded into the
// y-stage weights; per-row hoisted lgn gathers for MLP=3.
// ---------------------------------------------------------------------------
__global__ __launch_bounds__(512, 2) void seprot_main_kernel(
    const float* __restrict__ grid1, const float* __restrict__ grid2,
    const float* __restrict__ theta,
    const float* __restrict__ coefx, const float* __restrict__ coefy,
    const float* __restrict__ coefr, float* __restrict__ out)
{
    __shared__ float4 sx[1024];   // fp32 coefx table (prologue only)
    __shared__ float4 sy[1024];   // fp32 coefy table; later: srh/sxh fp16 tables
    __shared__ float4 sr[1024];   // fp32 coefr table; later: output staging

    const int tid = threadIdx.x;

    // ---- stage 1: cooperative transposed + swizzled fp32 load ----
#pragma unroll
    for (int it = 0; it < 8; it++) {
        const int g   = tid + it * 512;
        const int nvq = g >> 8;
        const int a   = (g >> 6) & 3;
        const int c2  = (g >> 4) & 3;
        const int n   = g & 15;
        const int entry = n * 64 + nvq * 4 + (a ^ ((nvq >> 1) & 3));
        const int dst = entry * 4 + c2;
        ((float*)sx)[dst] = coefx[g];
        ((float*)sy)[dst] = coefy[g];
        ((float*)sr)[dst] = coefr[g];
    }
    __syncthreads();

    const int nv   = tid & 15;
    const int swz  = (nv >> 1) & 3;
    const int hswz = (nv >> 2) & 1;
    const int nv4  = nv * 4;
    const int nv2  = nv * 2;
    const int pl   = tid >> 4;                 // pixel within block, 0..31
    const int P    = blockIdx.x * 32 + pl;     // global pixel id
    const int b    = blockIdx.x >> 7;          // 128 blocks per batch

    const float2 g2 = ((const float2*)grid2)[P];   // warp-broadcast
    const float fx = rintf((g2.x + 1.0f) * 32.0f - 0.5f);
    const float fy = rintf((g2.y + 1.0f) * 32.0f - 0.5f);
    const bool qv = (fx >= 0.0f) && (fx <= 63.0f) && (fy >= 0.0f) && (fy <= 63.0f);

    // ---- stage 2: Cy (z interp, depends only on b,nv) ----
    const float zc  = theta[b] / 3.14159265358979323846f;
    const float gz  = (zc + 1.0f) * 8.0f - 0.5f;
    const float z0f = floorf(gz);
    const int   z0  = (int)z0f;
    const float wz1 = gz - z0f;
    const float wz0e = (z0 >= 0 && z0 <= 15) ? (1.0f - wz1) : 0.0f;
    const float wz1e = (z0 + 1 >= 0 && z0 + 1 <= 15) ? wz1 : 0.0f;
    const int iz0 = min(max(z0, 0), 15);
    const int iz1 = min(max(z0 + 1, 0), 15);
    const int zb0 = iz0 * 64 + nv4, zb1 = iz1 * 64 + nv4;

    float4 Cy[4];
#pragma unroll
    for (int kp = 0; kp < 4; kp++) {
        const float4 a0 = sy[zb0 + (kp ^ swz)];
        const float4 a1 = sy[zb1 + (kp ^ swz)];
        Cy[kp].x = wz0e * a0.x + wz1e * a1.x;
        Cy[kp].y = wz0e * a0.y + wz1e * a1.y;
        Cy[kp].z = wz0e * a0.z + wz1e * a1.z;
        Cy[kp].w = wz0e * a0.w + wz1e * a1.w;
    }
    __syncthreads();   // all reads of fp32 sy done; its memory is repurposed

    // ---- stage 3: build fp16 tables (into sy's memory) ----
    uint4* srh = (uint4*)sy;           // 512 uint4 = 8KB : folded Cy@Cr
    uint4* sxh = ((uint4*)sy) + 512;   // 512 uint4 = 8KB : Cx
    {
        const int row  = pl >> 1;
        const int h    = pl & 1;
        const int base = row * 64 + nv4;
        const int unit = row * 32 + nv2 + (h ^ hswz);

        const float4 S0 = sr[base + (0 ^ swz)];
        const float4 S1 = sr[base + (1 ^ swz)];
        const float4 S2 = sr[base + (2 ^ swz)];
        const float4 S3 = sr[base + (3 ^ swz)];
        float4 R[4];
#pragma unroll
        for (int k = 0; k < 4; k++) {
            R[k].x = Cy[k].x*S0.x + Cy[k].y*S1.x + Cy[k].z*S2.x + Cy[k].w*S3.x;
            R[k].y = Cy[k].x*S0.y + Cy[k].y*S1.y + Cy[k].z*S2.y + Cy[k].w*S3.y;
            R[k].z = Cy[k].x*S0.z + Cy[k].y*S1.z + Cy[k].z*S2.z + Cy[k].w*S3.z;
            R[k].w = Cy[k].x*S0.w + Cy[k].y*S1.w + Cy[k].z*S2.w + Cy[k].w*S3.w;
        }
        const float4 RA = h ? R[2] : R[0];
        const float4 RB = h ? R[3] : R[1];
        uint4 u;
        u.x = pk(RA.x, RA.y); u.y = pk(RA.z, RA.w);
        u.z = pk(RB.x, RB.y); u.w = pk(RB.z, RB.w);
        srh[unit] = u;

        const float4 CA = sx[base + ((2 * h)     ^ swz)];
        const float4 CB = sx[base + ((2 * h + 1) ^ swz)];
        uint4 v;
        v.x = pk(CA.x, CA.y); v.y = pk(CA.z, CA.w);
        v.z = pk(CB.x, CB.y); v.w = pk(CB.z, CB.w);
        sxh[unit] = v;
    }
    __syncthreads();

    float acc0 = 0.0f, acc1 = 0.0f, acc2 = 0.0f, acc3 = 0.0f;

    if (qv) {
        const int qx = (int)fx, qy = (int)fy;
        const float4* lbase = (const float4*)g_lgn_cl + (size_t)b * (4096 * 16);
        const float2* g1base = (const float2*)grid1 + b * 4096;

#pragma unroll
        for (int di = -1; di <= 1; di++) {
            const int ty   = qy + di;
            const float rowv = ((unsigned)ty < 64u) ? 1.0f : 0.0f;
            const int tyc  = min(max(ty, 0), 63);

            // hoisted row loads: 3 lgn gathers in flight (clamped addresses)
            const int txc0 = min(max(qx - 1, 0), 63);
            const int txc1 = qx;
            const int txc2 = min(max(qx + 1, 0), 63);
            float4 Lr[3];
            Lr[0] = lbase[(tyc * 64 + txc0) * 16 + nv];
            Lr[1] = lbase[(tyc * 64 + txc1) * 16 + nv];
            Lr[2] = lbase[(tyc * 64 + txc2) * 16 + nv];
            float2 g1r[3];
            g1r[0] = g1base[tyc * 64 + txc0];
            g1r[1] = g1base[tyc * 64 + txc1];
            g1r[2] = g1base[tyc * 64 + txc2];

#pragma unroll
            for (int dj = 0; dj < 3; dj++) {
                const int tx = qx + dj - 1;
                const float vm = rowv * (((unsigned)tx < 64u) ? 1.0f : 0.0f);

                const float dx = g2.x - g1r[dj].x;
                const float dy = g2.y - g1r[dj].y;

                // ---- x-axis interp over folded table ----
                const float gx  = (dx + 1.0f) * 8.0f - 0.5f;
                const float x0f = floorf(gx);
                const int   x0  = (int)x0f;
                const float wx1 = gx - x0f;
                const float wx0e = (x0 >= 0 && x0 <= 15) ? (1.0f - wx1) : 0.0f;
                const float wx1e = (x0 + 1 >= 0 && x0 + 1 <= 15) ? wx1 : 0.0f;
                const int ix0 = min(max(x0, 0), 15);
                const int ix1 = min(max(x0 + 1, 0), 15);

                const float4 L = Lr[dj];

                const uint4 U0a = srh[ix0 * 32 + nv2 + (0 ^ hswz)];
                const uint4 U0b = srh[ix0 * 32 + nv2 + (1 ^ hswz)];
                const uint4 U1a = srh[ix1 * 32 + nv2 + (0 ^ hswz)];
                const uint4 U1b = srh[ix1 * 32 + nv2 + (1 ^ hswz)];

                const float u0 = wx0e * dot4(rv(U0a.x, U0a.y), L)
                               + wx1e * dot4(rv(U1a.x, U1a.y), L);
                const float u1 = wx0e * dot4(rv(U0a.z, U0a.w), L)
                               + wx1e * dot4(rv(U1a.z, U1a.w), L);
                const float u2 = wx0e * dot4(rv(U0b.x, U0b.y), L)
                               + wx1e * dot4(rv(U1b.x, U1b.y), L);
                const float u3 = wx0e * dot4(rv(U0b.z, U0b.w), L)
                               + wx1e * dot4(rv(U1b.z, U1b.w), L);
                const float4 u4 = make_float4(u0, u1, u2, u3);

                // ---- y-axis interp over Cx, validity folded into weights ----
                const float gy  = (dy + 1.0f) * 8.0f - 0.5f;
                const float y0f = floorf(gy);
                const int   y0  = (int)y0f;
                const float wy1 = gy - y0f;
                const float wy0e = vm * ((y0 >= 0 && y0 <= 15) ? (1.0f - wy1) : 0.0f);
                const float wy1e = vm * ((y0 + 1 >= 0 && y0 + 1 <= 15) ? wy1 : 0.0f);
                const int iy0 = min(max(y0, 0), 15);
                const int iy1 = min(max(y0 + 1, 0), 15);

                const uint4 V0a = sxh[iy0 * 32 + nv2 + (0 ^ hswz)];
                const uint4 V0b = sxh[iy0 * 32 + nv2 + (1 ^ hswz)];
                const uint4 V1a = sxh[iy1 * 32 + nv2 + (0 ^ hswz)];
                const uint4 V1b = sxh[iy1 * 32 + nv2 + (1 ^ hswz)];

                acc0 += wy0e * dot4(rv(V0a.x, V0a.y), u4)
                      + wy1e * dot4(rv(V1a.x, V1a.y), u4);
                acc1 += wy0e * dot4(rv(V0a.z, V0a.w), u4)
                      + wy1e * dot4(rv(V1a.z, V1a.w), u4);
                acc2 += wy0e * dot4(rv(V0b.x, V0b.y), u4)
                      + wy1e * dot4(rv(V1b.x, V1b.y), u4);
                acc3 += wy0e * dot4(rv(V0b.z, V0b.w), u4)
                      + wy1e * dot4(rv(V1b.z, V1b.w), u4);
            }
        }
    }

    // ---- stage outputs in smem (aliasing sr), then coalesced global stores ----
    float* so = (float*)sr;            // needs 64*33 = 2112 floats < 4096 avail
    __syncthreads();                   // ensure prologue reads of sr are done
    so[(nv4 + 0) * 33 + pl] = acc0;
    so[(nv4 + 1) * 33 + pl] = acc1;
    so[(nv4 + 2) * 33 + pl] = acc2;
    so[(nv4 + 3) * 33 + pl] = acc3;
    __syncthreads();

    // out layout (B, 64, 64, 64): 32 consecutive pixels per block, same batch
    const int rem0 = (blockIdx.x & 127) * 32;
    float* obase = out + (size_t)b * 64 * 4096 + rem0;
#pragma unroll
    for (int i2 = 0; i2 < 4; i2++) {
        const int idx = tid + i2 * 512;
        const int c = idx >> 5, px = idx & 31;
        obase[(size_t)c * 4096 + px] = so[c * 33 + px];
    }
}

extern "C" void kernel_launch(void* const* d_in, const int* in_sizes, int n_in,
                              void* d_out, int out_size) {
    const float* grid1 = (const float*)d_in[0];
    const float* grid2 = (const float*)d_in[1];
    const float* theta = (const float*)d_in[2];
    const float* lgn   = (const float*)d_in[3];
    const float* coefx = (const float*)d_in[4];
    const float* coefy = (const float*)d_in[5];
    const float* coefr = (const float*)d_in[6];
    float* out = (float*)d_out;

    transpose_lgn_kernel<<<dim3(2, 64, 4), 256>>>(lgn);
    seprot_main_kernel<<<512, 512>>>(grid1, grid2, theta, coefx, coefy, coefr, out);
}